// round 1
// baseline (speedup 1.0000x reference)
#include <cuda_runtime.h>
#include <math.h>

#define BB 2
#define SS 2048
#define HID 4096
#define NHQ 32
#define NHKV 8
#define HD 128
#define MR (BB*SS)          // 4096 rows
#define KVD (NHKV*HD)       // 1024
#define GRP (NHQ/NHKV)      // 4

// Scratch (allocation-free rule: __device__ globals)
__device__ float g_Q[MR*HID];     // 64 MB
__device__ float g_K[MR*KVD];     // 16 MB
__device__ float g_V[MR*KVD];     // 16 MB
__device__ float g_Att[MR*HID];   // 64 MB
__device__ float g_cos[SS*(HD/2)];
__device__ float g_sin[SS*(HD/2)];

// ---------------------------------------------------------------------------
// SGEMM: C[M,N] = A[M,K] @ B[K,N], all row-major, fp32.
// 128x128 block tile, BK=8, 8x8 per-thread tile, 256 threads.
// M,N,K assumed multiples of 128/128/8 (true for all calls here).
// ---------------------------------------------------------------------------
__global__ void __launch_bounds__(256) sgemm128(
    const float* __restrict__ A, const float* __restrict__ B,
    float* __restrict__ C, int M, int N, int K)
{
    __shared__ float As[8][128];
    __shared__ float Bs[8][128];
    const int tid = threadIdx.x;
    const int tx = tid & 15;          // 16 col-groups
    const int ty = tid >> 4;          // 16 row-groups

    const float* Ab = A + (size_t)blockIdx.y * 128 * K;
    const float* Bb = B + blockIdx.x * 128;

    float acc[8][8];
    #pragma unroll
    for (int i = 0; i < 8; i++)
        #pragma unroll
        for (int j = 0; j < 8; j++) acc[i][j] = 0.f;

    const int arow = tid >> 1;            // 0..127
    const int acol = (tid & 1) * 4;       // 0 or 4
    const int brow = tid >> 5;            // 0..7
    const int bcol = (tid & 31) * 4;      // 0..124

    for (int k0 = 0; k0 < K; k0 += 8) {
        float4 a4 = *(const float4*)(Ab + (size_t)arow * K + k0 + acol);
        As[acol + 0][arow] = a4.x;
        As[acol + 1][arow] = a4.y;
        As[acol + 2][arow] = a4.z;
        As[acol + 3][arow] = a4.w;
        *(float4*)(&Bs[brow][bcol]) =
            *(const float4*)(Bb + (size_t)(k0 + brow) * N + bcol);
        __syncthreads();
        #pragma unroll
        for (int kk = 0; kk < 8; kk++) {
            float ar[8], br[8];
            #pragma unroll
            for (int i = 0; i < 8; i++) ar[i] = As[kk][ty * 8 + i];
            #pragma unroll
            for (int j = 0; j < 8; j++) br[j] = Bs[kk][tx * 8 + j];
            #pragma unroll
            for (int i = 0; i < 8; i++)
                #pragma unroll
                for (int j = 0; j < 8; j++)
                    acc[i][j] = fmaf(ar[i], br[j], acc[i][j]);
        }
        __syncthreads();
    }

    float* Cb = C + (size_t)(blockIdx.y * 128 + ty * 8) * N + blockIdx.x * 128 + tx * 8;
    #pragma unroll
    for (int i = 0; i < 8; i++) {
        #pragma unroll
        for (int j = 0; j < 8; j += 4) {
            float4 v = make_float4(acc[i][j], acc[i][j+1], acc[i][j+2], acc[i][j+3]);
            *(float4*)(Cb + (size_t)i * N + j) = v;
        }
    }
}

// ---------------------------------------------------------------------------
// RoPE table: mimic the reference's f32 rounding exactly:
//   invf_f32 = fl32(10000^(-i/64));  ang_f32 = fl32(pos * invf_f32)
// then evaluate cos/sin of ang_f32 in double for ~1-ulp agreement.
// ---------------------------------------------------------------------------
__global__ void rope_table_k()
{
    int idx = blockIdx.x * blockDim.x + threadIdx.x;
    if (idx >= SS * 64) return;
    int pos = idx >> 6;
    int i   = idx & 63;
    float invf = (float)pow(10000.0, -((double)i) / 64.0);
    float angf = (float)pos * invf;
    double ang = (double)angf;
    g_cos[idx] = (float)cos(ang);
    g_sin[idx] = (float)sin(ang);
}

// X: [BB*SS, nh, HD]; rotate halves (d, d+64) per head.
__global__ void rope_apply_k(float* __restrict__ X, int nh)
{
    int idx = blockIdx.x * blockDim.x + threadIdx.x;
    int total = MR * nh * 64;
    if (idx >= total) return;
    int half = idx & 63;
    int h    = (idx >> 6) % nh;
    int r    = idx / (64 * nh);       // row = b*SS + s
    int s    = r % SS;
    size_t base = (size_t)r * nh * HD + (size_t)h * HD;
    float c  = g_cos[s * 64 + half];
    float sn = g_sin[s * 64 + half];
    float x1 = X[base + half];
    float x2 = X[base + half + 64];
    X[base + half]      = x1 * c - x2 * sn;
    X[base + half + 64] = x2 * c + x1 * sn;
}

// ---------------------------------------------------------------------------
// Causal GQA attention, flash-style online softmax.
// Block = 256 threads (8 warps), handles one (b, h, 64-query tile).
// Each warp owns 8 query rows. Lane owns k-cols {lane, lane+32} for scores
// and d-cols {lane, lane+32, lane+64, lane+96} for the output accumulator.
// Smem rows padded to 129 floats -> conflict-free column access.
// ---------------------------------------------------------------------------
#define PQ 129
#define ATTN_SMEM (3 * 64 * PQ * (int)sizeof(float))

__global__ void __launch_bounds__(256) attn_k()
{
    extern __shared__ float sm[];
    float* Qs = sm;
    float* Ks = sm + 64 * PQ;
    float* Vs = sm + 2 * 64 * PQ;

    const int qb = blockIdx.x, h = blockIdx.y, b = blockIdx.z;
    const int kvh = h / GRP;
    const int tid = threadIdx.x;
    const int w = tid >> 5, lane = tid & 31;
    const float scale = 0.08838834764831845f;  // 1/sqrt(128)

    // Load+scale Q tile
    for (int i = tid; i < 64 * HD; i += 256) {
        int r = i >> 7, d = i & 127;
        Qs[r * PQ + d] =
            g_Q[(size_t)(b * SS + qb * 64 + r) * HID + h * HD + d] * scale;
    }

    const int q0 = w * 8;
    float m[8], l[8], O[8][4];
    #pragma unroll
    for (int i = 0; i < 8; i++) {
        m[i] = -1e30f; l[i] = 0.f;
        O[i][0] = O[i][1] = O[i][2] = O[i][3] = 0.f;
    }

    for (int kt = 0; kt <= qb; kt++) {
        __syncthreads();  // previous tile's Ks/Vs fully consumed
        for (int i = tid; i < 64 * HD; i += 256) {
            int r = i >> 7, d = i & 127;
            size_t g = (size_t)(b * SS + kt * 64 + r) * KVD + kvh * HD + d;
            Ks[r * PQ + d] = g_K[g];
            Vs[r * PQ + d] = g_V[g];
        }
        __syncthreads();

        // --- scores S = Q K^T for this warp's 8 rows, lane's 2 k-cols ---
        float p0[8], p1[8];
        #pragma unroll
        for (int i = 0; i < 8; i++) { p0[i] = 0.f; p1[i] = 0.f; }
        #pragma unroll 4
        for (int d = 0; d < HD; d++) {
            float k0v = Ks[lane * PQ + d];
            float k1v = Ks[(lane + 32) * PQ + d];
            #pragma unroll
            for (int i = 0; i < 8; i++) {
                float qv = Qs[(q0 + i) * PQ + d];
                p0[i] = fmaf(qv, k0v, p0[i]);
                p1[i] = fmaf(qv, k1v, p1[i]);
            }
        }

        // --- causal mask + online softmax update ---
        const int kg = kt * 64;
        #pragma unroll
        for (int i = 0; i < 8; i++) {
            int qg = qb * 64 + q0 + i;
            float a  = (kg + lane      <= qg) ? p0[i] : -1e30f;
            float bq = (kg + lane + 32 <= qg) ? p1[i] : -1e30f;
            float mx = fmaxf(a, bq);
            #pragma unroll
            for (int o = 16; o; o >>= 1)
                mx = fmaxf(mx, __shfl_xor_sync(0xffffffffu, mx, o));
            float mn = fmaxf(m[i], mx);
            float e0 = __expf(a - mn);
            float e1 = __expf(bq - mn);
            float sum = e0 + e1;
            #pragma unroll
            for (int o = 16; o; o >>= 1)
                sum += __shfl_xor_sync(0xffffffffu, sum, o);
            float alpha = __expf(m[i] - mn);
            l[i] = l[i] * alpha + sum;
            m[i] = mn;
            O[i][0] *= alpha; O[i][1] *= alpha; O[i][2] *= alpha; O[i][3] *= alpha;
            p0[i] = e0; p1[i] = e1;
        }

        // --- O += P V (p broadcast via shuffle; Vs reads conflict-free) ---
        #pragma unroll 1
        for (int kc = 0; kc < 32; kc++) {
            float v0 = Vs[kc * PQ + lane];
            float v1 = Vs[kc * PQ + lane + 32];
            float v2 = Vs[kc * PQ + lane + 64];
            float v3 = Vs[kc * PQ + lane + 96];
            #pragma unroll
            for (int i = 0; i < 8; i++) {
                float p = __shfl_sync(0xffffffffu, p0[i], kc);
                O[i][0] = fmaf(p, v0, O[i][0]);
                O[i][1] = fmaf(p, v1, O[i][1]);
                O[i][2] = fmaf(p, v2, O[i][2]);
                O[i][3] = fmaf(p, v3, O[i][3]);
            }
        }
        #pragma unroll 1
        for (int kc = 0; kc < 32; kc++) {
            float v0 = Vs[(kc + 32) * PQ + lane];
            float v1 = Vs[(kc + 32) * PQ + lane + 32];
            float v2 = Vs[(kc + 32) * PQ + lane + 64];
            float v3 = Vs[(kc + 32) * PQ + lane + 96];
            #pragma unroll
            for (int i = 0; i < 8; i++) {
                float p = __shfl_sync(0xffffffffu, p1[i], kc);
                O[i][0] = fmaf(p, v0, O[i][0]);
                O[i][1] = fmaf(p, v1, O[i][1]);
                O[i][2] = fmaf(p, v2, O[i][2]);
                O[i][3] = fmaf(p, v3, O[i][3]);
            }
        }
    }

    // normalize + write [b,s,h,d] layout so final GEMM is plain row-major
    #pragma unroll
    for (int i = 0; i < 8; i++) {
        float inv = 1.0f / l[i];
        int qg = qb * 64 + q0 + i;
        size_t base = (size_t)(b * SS + qg) * HID + (size_t)h * HD;
        g_Att[base + lane]      = O[i][0] * inv;
        g_Att[base + lane + 32] = O[i][1] * inv;
        g_Att[base + lane + 64] = O[i][2] * inv;
        g_Att[base + lane + 96] = O[i][3] * inv;
    }
}

// ---------------------------------------------------------------------------
extern "C" void kernel_launch(void* const* d_in, const int* in_sizes, int n_in,
                              void* d_out, int out_size)
{
    (void)in_sizes; (void)n_in; (void)out_size;
    const float* x  = (const float*)d_in[0];
    const float* Wq = (const float*)d_in[1];
    const float* Wk = (const float*)d_in[2];
    const float* Wv = (const float*)d_in[3];
    const float* Wo = (const float*)d_in[4];
    float* out = (float*)d_out;

    float *Qp, *Kp, *Vp, *Ap;
    cudaGetSymbolAddress((void**)&Qp, g_Q);
    cudaGetSymbolAddress((void**)&Kp, g_K);
    cudaGetSymbolAddress((void**)&Vp, g_V);
    cudaGetSymbolAddress((void**)&Ap, g_Att);

    rope_table_k<<<(SS * 64 + 255) / 256, 256>>>();

    sgemm128<<<dim3(HID / 128, MR / 128), 256>>>(x, Wq, Qp, MR, HID, HID);
    sgemm128<<<dim3(KVD / 128, MR / 128), 256>>>(x, Wk, Kp, MR, KVD, HID);
    sgemm128<<<dim3(KVD / 128, MR / 128), 256>>>(x, Wv, Vp, MR, KVD, HID);

    rope_apply_k<<<(MR * NHQ  * 64 + 255) / 256, 256>>>(Qp, NHQ);
    rope_apply_k<<<(MR * NHKV * 64 + 255) / 256, 256>>>(Kp, NHKV);

    cudaFuncSetAttribute(attn_k, cudaFuncAttributeMaxDynamicSharedMemorySize, ATTN_SMEM);
    attn_k<<<dim3(SS / 64, NHQ, BB), 256, ATTN_SMEM>>>();

    sgemm128<<<dim3(HID / 128, MR / 128), 256>>>(Ap, Wo, out, MR, HID, HID);
}

// round 3
// speedup vs baseline: 1.2062x; 1.2062x over previous
#include <cuda_runtime.h>
#include <cuda_bf16.h>
#include <math.h>
#include <stdint.h>

#define BB 2
#define SS 2048
#define HID 4096
#define NHQ 32
#define NHKV 8
#define HD 128
#define MR (BB*SS)          // 4096 rows
#define KVD (NHKV*HD)       // 1024
#define GRP (NHQ/NHKV)      // 4

// ---------------- scratch (__device__ globals) ------------------------------
__device__ float g_Q[MR*HID];
__device__ float g_K[MR*KVD];
__device__ float g_V[MR*KVD];
__device__ float g_Att[MR*HID];
__device__ float g_cos[SS*(HD/2)];
__device__ float g_sin[SS*(HD/2)];
__device__ __nv_bfloat16 g_Qh[MR*HID], g_Ql[MR*HID];
__device__ __nv_bfloat16 g_Kh[MR*KVD], g_Kl[MR*KVD];
__device__ __nv_bfloat16 g_Vh[MR*KVD], g_Vl[MR*KVD];

// ---------------- PTX helpers (portable: sm_80-era ops only) ----------------
__device__ __forceinline__ uint32_t su32(const void* p) {
    uint32_t a;
    asm("{ .reg .u64 t; cvta.to.shared.u64 t, %1; cvt.u32.u64 %0, t; }"
        : "=r"(a) : "l"(p));
    return a;
}
__device__ __forceinline__ void cp16(uint32_t sa, const void* g) {
    asm volatile("cp.async.cg.shared.global [%0], [%1], 16;\n" :: "r"(sa), "l"(g));
}
#define CP_COMMIT() asm volatile("cp.async.commit_group;\n")
#define LDSM_X4(r, a) \
    asm volatile("ldmatrix.sync.aligned.m8n8.x4.shared.b16 {%0,%1,%2,%3}, [%4];" \
        : "=r"((r)[0]), "=r"((r)[1]), "=r"((r)[2]), "=r"((r)[3]) : "r"(a))
#define LDSM_X4T(r, a) \
    asm volatile("ldmatrix.sync.aligned.m8n8.x4.trans.shared.b16 {%0,%1,%2,%3}, [%4];" \
        : "=r"((r)[0]), "=r"((r)[1]), "=r"((r)[2]), "=r"((r)[3]) : "r"(a))
#define MMA4(d, a, b0, b1) \
    asm volatile("mma.sync.aligned.m16n8k16.row.col.f32.bf16.bf16.f32 " \
        "{%0,%1,%2,%3},{%4,%5,%6,%7},{%8,%9},{%0,%1,%2,%3};" \
        : "+f"((d)[0]), "+f"((d)[1]), "+f"((d)[2]), "+f"((d)[3]) \
        : "r"((a)[0]), "r"((a)[1]), "r"((a)[2]), "r"((a)[3]), "r"(b0), "r"(b1))

// 256-byte-row swizzle: rotate 16B blocks within a row by (row % 8)
__device__ __forceinline__ uint32_t swz256(uint32_t o) {
    return o ^ (((o >> 8) & 7u) << 4);
}
// pack two floats into bf16x2 hi and lo (split precision)
__device__ __forceinline__ void pk2(float x, float y, uint32_t& hi, uint32_t& lo) {
    __nv_bfloat16 hx = __float2bfloat16(x), hy = __float2bfloat16(y);
    hi = ((uint32_t)*(uint16_t*)&hy << 16) | *(uint16_t*)&hx;
    __nv_bfloat16 lx = __float2bfloat16(x - __bfloat162float(hx));
    __nv_bfloat16 ly = __float2bfloat16(y - __bfloat162float(hy));
    lo = ((uint32_t)*(uint16_t*)&ly << 16) | *(uint16_t*)&lx;
}

// ---------------------------------------------------------------------------
// SGEMM (proven R1 kernel): C[M,N] = A[M,K] @ B[K,N], fp32 row-major.
// ---------------------------------------------------------------------------
__global__ void __launch_bounds__(256) sgemm128(
    const float* __restrict__ A, const float* __restrict__ B,
    float* __restrict__ C, int M, int N, int K)
{
    __shared__ float As[8][128];
    __shared__ float Bs[8][128];
    const int tid = threadIdx.x;
    const int tx = tid & 15;
    const int ty = tid >> 4;

    const float* Ab = A + (size_t)blockIdx.y * 128 * K;
    const float* Bb = B + blockIdx.x * 128;

    float acc[8][8];
    #pragma unroll
    for (int i = 0; i < 8; i++)
        #pragma unroll
        for (int j = 0; j < 8; j++) acc[i][j] = 0.f;

    const int arow = tid >> 1;
    const int acol = (tid & 1) * 4;
    const int brow = tid >> 5;
    const int bcol = (tid & 31) * 4;

    for (int k0 = 0; k0 < K; k0 += 8) {
        float4 a4 = *(const float4*)(Ab + (size_t)arow * K + k0 + acol);
        As[acol + 0][arow] = a4.x;
        As[acol + 1][arow] = a4.y;
        As[acol + 2][arow] = a4.z;
        As[acol + 3][arow] = a4.w;
        *(float4*)(&Bs[brow][bcol]) =
            *(const float4*)(Bb + (size_t)(k0 + brow) * N + bcol);
        __syncthreads();
        #pragma unroll
        for (int kk = 0; kk < 8; kk++) {
            float ar[8], br[8];
            #pragma unroll
            for (int i = 0; i < 8; i++) ar[i] = As[kk][ty * 8 + i];
            #pragma unroll
            for (int j = 0; j < 8; j++) br[j] = Bs[kk][tx * 8 + j];
            #pragma unroll
            for (int i = 0; i < 8; i++)
                #pragma unroll
                for (int j = 0; j < 8; j++)
                    acc[i][j] = fmaf(ar[i], br[j], acc[i][j]);
        }
        __syncthreads();
    }

    float* Cb = C + (size_t)(blockIdx.y * 128 + ty * 8) * N + blockIdx.x * 128 + tx * 8;
    #pragma unroll
    for (int i = 0; i < 8; i++) {
        #pragma unroll
        for (int j = 0; j < 8; j += 4) {
            float4 v = make_float4(acc[i][j], acc[i][j+1], acc[i][j+2], acc[i][j+3]);
            *(float4*)(Cb + (size_t)i * N + j) = v;
        }
    }
}

// ---------------------------------------------------------------------------
// RoPE table (reference-exact f32 rounding of angles)
// ---------------------------------------------------------------------------
__global__ void rope_table_k()
{
    int idx = blockIdx.x * blockDim.x + threadIdx.x;
    if (idx >= SS * 64) return;
    int pos = idx >> 6;
    int i   = idx & 63;
    float invf = (float)pow(10000.0, -((double)i) / 64.0);
    float angf = (float)pos * invf;
    double ang = (double)angf;
    g_cos[idx] = (float)cos(ang);
    g_sin[idx] = (float)sin(ang);
}

// Read fp32 [MR, nh*HD], rotate halves, scale, write split hi/lo bf16.
__global__ void rope_split_k(const float* __restrict__ X,
                             __nv_bfloat16* __restrict__ H,
                             __nv_bfloat16* __restrict__ L,
                             int nh, float scale)
{
    int idx = blockIdx.x * blockDim.x + threadIdx.x;
    int total = MR * nh * 64;
    if (idx >= total) return;
    int half = idx & 63;
    int h    = (idx >> 6) % nh;
    int r    = idx / (64 * nh);
    int s    = r % SS;
    size_t base = (size_t)r * nh * HD + (size_t)h * HD;
    float c  = g_cos[s * 64 + half];
    float sn = g_sin[s * 64 + half];
    float x1 = X[base + half];
    float x2 = X[base + half + 64];
    float y1 = (x1 * c - x2 * sn) * scale;
    float y2 = (x2 * c + x1 * sn) * scale;
    __nv_bfloat16 h1 = __float2bfloat16(y1);
    __nv_bfloat16 h2 = __float2bfloat16(y2);
    H[base + half]      = h1;
    H[base + half + 64] = h2;
    L[base + half]      = __float2bfloat16(y1 - __bfloat162float(h1));
    L[base + half + 64] = __float2bfloat16(y2 - __bfloat162float(h2));
}

__global__ void cvt_hl(const float* __restrict__ X,
                       __nv_bfloat16* __restrict__ H, __nv_bfloat16* __restrict__ L, int n)
{
    int i = blockIdx.x * 256 + threadIdx.x;
    if (i >= n) return;
    float v = X[i];
    __nv_bfloat16 h = __float2bfloat16(v);
    H[i] = h;
    L[i] = __float2bfloat16(v - __bfloat162float(h));
}

// ---------------------------------------------------------------------------
// FlashAttention-2 with mma.sync bf16 (split-precision, 3-pass products).
// CTA: 128 q-rows, one (b,h); 8 warps, warp = 16 q-rows. BK=64.
// smem: Qh|Ql [128][128] bf16 (64KB) + 2 stages x {Kh,Kl,Vh,Vl}[64][128] (128KB)
// ---------------------------------------------------------------------------
#define ATT_SMEM 196608

__global__ void __launch_bounds__(256) attn_mma()
{
    extern __shared__ __align__(1024) char smdyn[];
    const int qb = blockIdx.x, h = blockIdx.y, b = blockIdx.z;
    const int kvh = h / GRP;
    const int tid = threadIdx.x, w = tid >> 5, l = tid & 31;
    const uint32_t sb = su32(smdyn);
    const uint32_t Qh_s = sb;                 // +32768 => Ql
    const uint32_t KV0  = sb + 65536;         // stage stride 65536
                                              // offs: Kh 0, Kl 16384, Vh 32768, Vl 49152

    // ---- load Q (hi+lo) ----
    {
        const __nv_bfloat16* qh = g_Qh + (size_t)(b * SS + qb * 128) * HID + h * HD;
        const __nv_bfloat16* ql = g_Ql + (size_t)(b * SS + qb * 128) * HID + h * HD;
        #pragma unroll
        for (int t = 0; t < 8; t++) {
            int j = tid + t * 256;            // 0..2047
            int r = j >> 4, c = j & 15;
            uint32_t o = swz256((uint32_t)(r * 256 + c * 16));
            cp16(Qh_s + o,         (const void*)(qh + (size_t)r * HID + c * 8));
            cp16(Qh_s + 32768 + o, (const void*)(ql + (size_t)r * HID + c * 8));
        }
        CP_COMMIT();
    }

    const int NT = 2 * qb + 2;
    auto loadKV = [&](int kt) {
        const uint32_t st = KV0 + (uint32_t)(kt & 1) * 65536;
        const size_t rb = (size_t)(b * SS + kt * 64) * KVD + kvh * HD;
        #pragma unroll
        for (int t = 0; t < 4; t++) {
            int j = tid + t * 256;            // 0..1023
            int r = j >> 4, c = j & 15;
            uint32_t o = swz256((uint32_t)(r * 256 + c * 16));
            size_t g = rb + (size_t)r * KVD + c * 8;
            cp16(st +         o, (const void*)(g_Kh + g));
            cp16(st + 16384 + o, (const void*)(g_Kl + g));
            cp16(st + 32768 + o, (const void*)(g_Vh + g));
            cp16(st + 49152 + o, (const void*)(g_Vl + g));
        }
        CP_COMMIT();
    };
    loadKV(0);

    const int m0 = w * 16;
    const int qg0 = qb * 128 + m0 + (l >> 2);   // warp row (lane group)
    float O[16][4];
    #pragma unroll
    for (int f = 0; f < 16; f++)
        { O[f][0] = 0.f; O[f][1] = 0.f; O[f][2] = 0.f; O[f][3] = 0.f; }
    float mr0 = -1e30f, mr1 = -1e30f, sl0 = 0.f, sl1 = 0.f;

    for (int kt = 0; kt < NT; kt++) {
        if (kt + 1 < NT) {
            loadKV(kt + 1);
            asm volatile("cp.async.wait_group 1;\n");
        } else {
            asm volatile("cp.async.wait_group 0;\n");
        }
        __syncthreads();

        const uint32_t st = KV0 + (uint32_t)(kt & 1) * 65536;

        // ---------- S = Q K^T (3-pass split) ----------
        float s[8][4];
        #pragma unroll
        for (int nb = 0; nb < 8; nb++)
            { s[nb][0] = 0.f; s[nb][1] = 0.f; s[nb][2] = 0.f; s[nb][3] = 0.f; }

        #pragma unroll
        for (int ks = 0; ks < 8; ks++) {
            uint32_t aQh[4], aQl[4];
            uint32_t aaddr = Qh_s + swz256(
                (uint32_t)((m0 + (l & 15)) * 256 + ks * 32 + ((l & 16) ? 16 : 0)));
            LDSM_X4(aQh, aaddr);
            LDSM_X4(aQl, aaddr + 32768);
            #pragma unroll
            for (int nb2 = 0; nb2 < 4; nb2++) {
                uint32_t brow = (uint32_t)(nb2 * 16 + (l & 7) + ((l & 16) ? 8 : 0));
                uint32_t baddr = st + swz256(brow * 256 + ks * 32 + ((l & 8) ? 16 : 0));
                uint32_t bh[4], bl[4];
                LDSM_X4(bh, baddr);
                LDSM_X4(bl, baddr + 16384);
                MMA4(s[2*nb2],   aQh, bh[0], bh[1]);
                MMA4(s[2*nb2+1], aQh, bh[2], bh[3]);
                MMA4(s[2*nb2],   aQh, bl[0], bl[1]);
                MMA4(s[2*nb2+1], aQh, bl[2], bl[3]);
                MMA4(s[2*nb2],   aQl, bh[0], bh[1]);
                MMA4(s[2*nb2+1], aQl, bh[2], bh[3]);
            }
        }

        // ---------- causal mask + online softmax ----------
        const int kgb = kt * 64 + (l & 3) * 2;
        float mx0 = -1e30f, mx1 = -1e30f;
        #pragma unroll
        for (int nb = 0; nb < 8; nb++) {
            int kg = kgb + nb * 8;
            if (kg     > qg0)     s[nb][0] = -1e30f;
            if (kg + 1 > qg0)     s[nb][1] = -1e30f;
            if (kg     > qg0 + 8) s[nb][2] = -1e30f;
            if (kg + 1 > qg0 + 8) s[nb][3] = -1e30f;
            mx0 = fmaxf(mx0, fmaxf(s[nb][0], s[nb][1]));
            mx1 = fmaxf(mx1, fmaxf(s[nb][2], s[nb][3]));
        }
        mx0 = fmaxf(mx0, __shfl_xor_sync(0xffffffffu, mx0, 1));
        mx0 = fmaxf(mx0, __shfl_xor_sync(0xffffffffu, mx0, 2));
        mx1 = fmaxf(mx1, __shfl_xor_sync(0xffffffffu, mx1, 1));
        mx1 = fmaxf(mx1, __shfl_xor_sync(0xffffffffu, mx1, 2));

        float mn0 = fmaxf(mr0, mx0), mn1 = fmaxf(mr1, mx1);
        float al0 = __expf(mr0 - mn0), al1 = __expf(mr1 - mn1);
        mr0 = mn0; mr1 = mn1;
        float sum0 = 0.f, sum1 = 0.f;
        #pragma unroll
        for (int nb = 0; nb < 8; nb++) {
            s[nb][0] = __expf(s[nb][0] - mn0);
            s[nb][1] = __expf(s[nb][1] - mn0);
            s[nb][2] = __expf(s[nb][2] - mn1);
            s[nb][3] = __expf(s[nb][3] - mn1);
            sum0 += s[nb][0] + s[nb][1];
            sum1 += s[nb][2] + s[nb][3];
        }
        sum0 += __shfl_xor_sync(0xffffffffu, sum0, 1);
        sum0 += __shfl_xor_sync(0xffffffffu, sum0, 2);
        sum1 += __shfl_xor_sync(0xffffffffu, sum1, 1);
        sum1 += __shfl_xor_sync(0xffffffffu, sum1, 2);
        sl0 = sl0 * al0 + sum0;
        sl1 = sl1 * al1 + sum1;
        #pragma unroll
        for (int f = 0; f < 16; f++) {
            O[f][0] *= al0; O[f][1] *= al0; O[f][2] *= al1; O[f][3] *= al1;
        }

        // ---------- O += P V (split P, split V) ----------
        #pragma unroll
        for (int j = 0; j < 4; j++) {
            uint32_t ph[4], pl[4];
            pk2(s[2*j][0],   s[2*j][1],   ph[0], pl[0]);
            pk2(s[2*j][2],   s[2*j][3],   ph[1], pl[1]);
            pk2(s[2*j+1][0], s[2*j+1][1], ph[2], pl[2]);
            pk2(s[2*j+1][2], s[2*j+1][3], ph[3], pl[3]);
            uint32_t vrow = (uint32_t)(j * 16 + (l & 7) + ((l & 8) ? 8 : 0));
            #pragma unroll
            for (int nb2 = 0; nb2 < 8; nb2++) {
                uint32_t vaddr = st + 32768 +
                    swz256(vrow * 256 + nb2 * 32 + ((l & 16) ? 16 : 0));
                uint32_t vh[4], vl[4];
                LDSM_X4T(vh, vaddr);
                LDSM_X4T(vl, vaddr + 16384);
                MMA4(O[2*nb2],   ph, vh[0], vh[1]);
                MMA4(O[2*nb2+1], ph, vh[2], vh[3]);
                MMA4(O[2*nb2],   ph, vl[0], vl[1]);
                MMA4(O[2*nb2+1], ph, vl[2], vl[3]);
                MMA4(O[2*nb2],   pl, vh[0], vh[1]);
                MMA4(O[2*nb2+1], pl, vh[2], vh[3]);
            }
        }
        __syncthreads();   // stage consumed; next iter may overwrite
    }

    // ---------- epilogue: normalize + store fp32 ----------
    const float i0 = 1.0f / sl0, i1 = 1.0f / sl1;
    float* o0 = g_Att + (size_t)(b * SS + qg0) * HID + h * HD;
    float* o1 = o0 + (size_t)8 * HID;
    #pragma unroll
    for (int nb = 0; nb < 16; nb++) {
        int col = nb * 8 + (l & 3) * 2;
        *(float2*)(o0 + col) = make_float2(O[nb][0] * i0, O[nb][1] * i0);
        *(float2*)(o1 + col) = make_float2(O[nb][2] * i1, O[nb][3] * i1);
    }
}

// ---------------------------------------------------------------------------
extern "C" void kernel_launch(void* const* d_in, const int* in_sizes, int n_in,
                              void* d_out, int out_size)
{
    (void)in_sizes; (void)n_in; (void)out_size;
    const float* x  = (const float*)d_in[0];
    const float* Wq = (const float*)d_in[1];
    const float* Wk = (const float*)d_in[2];
    const float* Wv = (const float*)d_in[3];
    const float* Wo = (const float*)d_in[4];
    float* out = (float*)d_out;

    float *Qp, *Kp, *Vp, *Ap;
    __nv_bfloat16 *qh, *ql, *kh, *kl, *vh, *vl;
    cudaGetSymbolAddress((void**)&Qp, g_Q);
    cudaGetSymbolAddress((void**)&Kp, g_K);
    cudaGetSymbolAddress((void**)&Vp, g_V);
    cudaGetSymbolAddress((void**)&Ap, g_Att);
    cudaGetSymbolAddress((void**)&qh, g_Qh); cudaGetSymbolAddress((void**)&ql, g_Ql);
    cudaGetSymbolAddress((void**)&kh, g_Kh); cudaGetSymbolAddress((void**)&kl, g_Kl);
    cudaGetSymbolAddress((void**)&vh, g_Vh); cudaGetSymbolAddress((void**)&vl, g_Vl);

    cudaFuncSetAttribute(attn_mma, cudaFuncAttributeMaxDynamicSharedMemorySize, ATT_SMEM);

    rope_table_k<<<(SS * 64 + 255) / 256, 256>>>();

    sgemm128<<<dim3(HID / 128, MR / 128), 256>>>(x, Wq, Qp, MR, HID, HID);
    sgemm128<<<dim3(KVD / 128, MR / 128), 256>>>(x, Wk, Kp, MR, KVD, HID);
    sgemm128<<<dim3(KVD / 128, MR / 128), 256>>>(x, Wv, Vp, MR, KVD, HID);

    const float scale = 0.08838834764831845f;   // 1/sqrt(128)
    rope_split_k<<<(MR * NHQ  * 64 + 255) / 256, 256>>>(Qp, qh, ql, NHQ, scale);
    rope_split_k<<<(MR * NHKV * 64 + 255) / 256, 256>>>(Kp, kh, kl, NHKV, 1.0f);
    cvt_hl<<<(MR * KVD + 255) / 256, 256>>>(Vp, vh, vl, MR * KVD);

    attn_mma<<<dim3(SS / 128, NHQ, BB), 256, ATT_SMEM>>>();

    sgemm128<<<dim3(HID / 128, MR / 128), 256>>>(Ap, Wo, out, MR, HID, HID);
}

// round 7
// speedup vs baseline: 3.6639x; 3.0377x over previous
#include <cuda_runtime.h>
#include <cuda_bf16.h>
#include <math.h>
#include <stdint.h>

#define BB 2
#define SS 2048
#define HID 4096
#define NHQ 32
#define NHKV 8
#define HD 128
#define MR (BB*SS)          // 4096 rows
#define KVD (NHKV*HD)       // 1024
#define GRP (NHQ/NHKV)      // 4
#define GK 4096             // all GEMMs have K=4096

// ---------------- scratch (__device__ globals) ------------------------------
__device__ float g_Q[MR*HID];
__device__ float g_K[MR*KVD];
__device__ float g_cos[SS*(HD/2)];
__device__ float g_sin[SS*(HD/2)];
__device__ __nv_bfloat16 g_xh[MR*HID],  g_xl[MR*HID];
__device__ __nv_bfloat16 g_Wqh[HID*HID], g_Wql[HID*HID];
__device__ __nv_bfloat16 g_Wkh[HID*KVD], g_Wkl[HID*KVD];
__device__ __nv_bfloat16 g_Wvh[HID*KVD], g_Wvl[HID*KVD];
__device__ __nv_bfloat16 g_Woh[HID*HID], g_Wol[HID*HID];
__device__ __nv_bfloat16 g_Qh[MR*HID], g_Ql[MR*HID];
__device__ __nv_bfloat16 g_Kh[MR*KVD], g_Kl[MR*KVD];
__device__ __nv_bfloat16 g_Vh[MR*KVD], g_Vl[MR*KVD];
__device__ __nv_bfloat16 g_Ath[MR*HID], g_Atl[MR*HID];

// ---------------- PTX helpers (portable sm_80-era ops) ----------------------
__device__ __forceinline__ uint32_t su32(const void* p) {
    uint32_t a;
    asm("{ .reg .u64 t; cvta.to.shared.u64 t, %1; cvt.u32.u64 %0, t; }"
        : "=r"(a) : "l"(p));
    return a;
}
__device__ __forceinline__ void cp16(uint32_t sa, const void* g) {
    asm volatile("cp.async.cg.shared.global [%0], [%1], 16;\n" :: "r"(sa), "l"(g));
}
#define CP_COMMIT() asm volatile("cp.async.commit_group;\n")
#define LDSM_X4(r, a) \
    asm volatile("ldmatrix.sync.aligned.m8n8.x4.shared.b16 {%0,%1,%2,%3}, [%4];" \
        : "=r"((r)[0]), "=r"((r)[1]), "=r"((r)[2]), "=r"((r)[3]) : "r"(a))
#define LDSM_X4T(r, a) \
    asm volatile("ldmatrix.sync.aligned.m8n8.x4.trans.shared.b16 {%0,%1,%2,%3}, [%4];" \
        : "=r"((r)[0]), "=r"((r)[1]), "=r"((r)[2]), "=r"((r)[3]) : "r"(a))
#define MMA4(d, a, b0, b1) \
    asm volatile("mma.sync.aligned.m16n8k16.row.col.f32.bf16.bf16.f32 " \
        "{%0,%1,%2,%3},{%4,%5,%6,%7},{%8,%9},{%0,%1,%2,%3};" \
        : "+f"((d)[0]), "+f"((d)[1]), "+f"((d)[2]), "+f"((d)[3]) \
        : "r"((a)[0]), "r"((a)[1]), "r"((a)[2]), "r"((a)[3]), "r"(b0), "r"(b1))

__device__ __forceinline__ uint32_t swz256(uint32_t o) {   // 256B rows
    return o ^ (((o >> 8) & 7u) << 4);
}
__device__ __forceinline__ uint32_t swz128(uint32_t o) {   // 128B rows
    return o ^ (((o >> 7) & 7u) << 4);
}
__device__ __forceinline__ void pk2(float x, float y, uint32_t& hi, uint32_t& lo) {
    __nv_bfloat16 hx = __float2bfloat16(x), hy = __float2bfloat16(y);
    hi = ((uint32_t)*(uint16_t*)&hy << 16) | *(uint16_t*)&hx;
    __nv_bfloat16 lx = __float2bfloat16(x - __bfloat162float(hx));
    __nv_bfloat16 ly = __float2bfloat16(y - __bfloat162float(hy));
    lo = ((uint32_t)*(uint16_t*)&ly << 16) | *(uint16_t*)&lx;
}

// ---------------------------------------------------------------------------
// Split-bf16 tensor-core GEMM: C[M,N] = A[M,4096] @ B[4096,N]
// A hi/lo bf16 row-major; B hi/lo bf16 row-major. 3-pass (AhBh+AhBl+AlBh).
// CTA 128x128, BK=64, double-buffered cp.async. 8 warps = 2m x 4n of 64x32.
// Output: fp32 (Cf) or split hi/lo bf16 (Oh/Ol) if Cf==nullptr.
// ---------------------------------------------------------------------------
#define GEMM_SMEM 131072

__global__ void __launch_bounds__(256) gemm_bf16s(
    const __nv_bfloat16* __restrict__ Ah, const __nv_bfloat16* __restrict__ Al,
    const __nv_bfloat16* __restrict__ Bh, const __nv_bfloat16* __restrict__ Bl,
    float* __restrict__ Cf,
    __nv_bfloat16* __restrict__ Oh, __nv_bfloat16* __restrict__ Ol, int N)
{
    extern __shared__ __align__(1024) char smg[];
    const uint32_t sb = su32(smg);
    const int tid = threadIdx.x, w = tid >> 5, l = tid & 31;
    const int n0 = blockIdx.x * 128, m0 = blockIdx.y * 128;
    const int wm = (w & 1) * 64, wn = (w >> 1) * 32;

    auto loadChunk = [&](int c) {
        const uint32_t st = sb + (uint32_t)(c & 1) * 65536;
        const int k0 = c * 64;
        #pragma unroll
        for (int t = 0; t < 4; t++) {                 // A: [128 m][64 k], 128B rows
            int j = tid + t * 256;
            int r = j >> 3, cc = j & 7;
            uint32_t o = swz128((uint32_t)(r * 128 + cc * 16));
            size_t g = (size_t)(m0 + r) * GK + k0 + cc * 8;
            cp16(st + o,         (const void*)(Ah + g));
            cp16(st + 16384 + o, (const void*)(Al + g));
        }
        #pragma unroll
        for (int t = 0; t < 4; t++) {                 // B: [64 k][128 n], 256B rows
            int j = tid + t * 256;
            int r = j >> 4, cc = j & 15;
            uint32_t o = swz256((uint32_t)(r * 256 + cc * 16));
            size_t g = (size_t)(k0 + r) * N + n0 + cc * 8;
            cp16(st + 32768 + o, (const void*)(Bh + g));
            cp16(st + 49152 + o, (const void*)(Bl + g));
        }
        CP_COMMIT();
    };

    float acc[4][4][4];
    #pragma unroll
    for (int mf = 0; mf < 4; mf++)
        #pragma unroll
        for (int nf = 0; nf < 4; nf++)
            { acc[mf][nf][0]=0.f; acc[mf][nf][1]=0.f; acc[mf][nf][2]=0.f; acc[mf][nf][3]=0.f; }

    loadChunk(0);

    const int NC = GK / 64;
    for (int c = 0; c < NC; c++) {
        if (c + 1 < NC) {
            loadChunk(c + 1);
            asm volatile("cp.async.wait_group 1;\n");
        } else {
            asm volatile("cp.async.wait_group 0;\n");
        }
        __syncthreads();
        const uint32_t st = sb + (uint32_t)(c & 1) * 65536;

        #pragma unroll
        for (int ks = 0; ks < 4; ks++) {
            uint32_t ah[4][4], alr[4][4];
            #pragma unroll
            for (int mf = 0; mf < 4; mf++) {
                uint32_t adr = st + swz128((uint32_t)(
                    (wm + mf * 16 + (l & 15)) * 128 + ks * 32 + ((l & 16) ? 16 : 0)));
                LDSM_X4(ah[mf], adr);
                LDSM_X4(alr[mf], adr + 16384);
            }
            #pragma unroll
            for (int g = 0; g < 2; g++) {
                uint32_t br = (uint32_t)(ks * 16 + (l & 7) + ((l & 8) ? 8 : 0));
                uint32_t bc = (uint32_t)((wn + g * 16) * 2 + ((l & 16) ? 16 : 0));
                uint32_t badr = st + 32768 + swz256(br * 256 + bc);
                uint32_t bh[4], bl[4];
                LDSM_X4T(bh, badr);
                LDSM_X4T(bl, badr + 16384);
                #pragma unroll
                for (int mf = 0; mf < 4; mf++) {
                    MMA4(acc[mf][2*g],   ah[mf],  bh[0], bh[1]);
                    MMA4(acc[mf][2*g+1], ah[mf],  bh[2], bh[3]);
                    MMA4(acc[mf][2*g],   ah[mf],  bl[0], bl[1]);
                    MMA4(acc[mf][2*g+1], ah[mf],  bl[2], bl[3]);
                    MMA4(acc[mf][2*g],   alr[mf], bh[0], bh[1]);
                    MMA4(acc[mf][2*g+1], alr[mf], bh[2], bh[3]);
                }
            }
        }
        __syncthreads();
    }

    // epilogue
    #pragma unroll
    for (int mf = 0; mf < 4; mf++) {
        int r0 = m0 + wm + mf * 16 + (l >> 2);
        #pragma unroll
        for (int nf = 0; nf < 4; nf++) {
            int cc = n0 + wn + nf * 8 + (l & 3) * 2;
            if (Cf) {
                *(float2*)(Cf + (size_t)r0 * N + cc) =
                    make_float2(acc[mf][nf][0], acc[mf][nf][1]);
                *(float2*)(Cf + (size_t)(r0 + 8) * N + cc) =
                    make_float2(acc[mf][nf][2], acc[mf][nf][3]);
            } else {
                uint32_t hi, lo;
                pk2(acc[mf][nf][0], acc[mf][nf][1], hi, lo);
                *(uint32_t*)(Oh + (size_t)r0 * N + cc) = hi;
                *(uint32_t*)(Ol + (size_t)r0 * N + cc) = lo;
                pk2(acc[mf][nf][2], acc[mf][nf][3], hi, lo);
                *(uint32_t*)(Oh + (size_t)(r0 + 8) * N + cc) = hi;
                *(uint32_t*)(Ol + (size_t)(r0 + 8) * N + cc) = lo;
            }
        }
    }
}

// ---------------------------------------------------------------------------
// conversions & RoPE
// ---------------------------------------------------------------------------
__global__ void cvt_hl(const float* __restrict__ X,
                       __nv_bfloat16* __restrict__ H, __nv_bfloat16* __restrict__ L, int n)
{
    int i = blockIdx.x * 256 + threadIdx.x;
    if (i >= n) return;
    float v = X[i];
    __nv_bfloat16 h = __float2bfloat16(v);
    H[i] = h;
    L[i] = __float2bfloat16(v - __bfloat162float(h));
}

__global__ void rope_table_k()
{
    int idx = blockIdx.x * blockDim.x + threadIdx.x;
    if (idx >= SS * 64) return;
    int pos = idx >> 6;
    int i   = idx & 63;
    float invf = (float)pow(10000.0, -((double)i) / 64.0);
    float angf = (float)pos * invf;
    double ang = (double)angf;
    g_cos[idx] = (float)cos(ang);
    g_sin[idx] = (float)sin(ang);
}

__global__ void rope_split_k(const float* __restrict__ X,
                             __nv_bfloat16* __restrict__ H,
                             __nv_bfloat16* __restrict__ L,
                             int nh, float scale)
{
    int idx = blockIdx.x * blockDim.x + threadIdx.x;
    int total = MR * nh * 64;
    if (idx >= total) return;
    int half = idx & 63;
    int h    = (idx >> 6) % nh;
    int r    = idx / (64 * nh);
    int s    = r % SS;
    size_t base = (size_t)r * nh * HD + (size_t)h * HD;
    float c  = g_cos[s * 64 + half];
    float sn = g_sin[s * 64 + half];
    float x1 = X[base + half];
    float x2 = X[base + half + 64];
    float y1 = (x1 * c - x2 * sn) * scale;
    float y2 = (x2 * c + x1 * sn) * scale;
    __nv_bfloat16 h1 = __float2bfloat16(y1);
    __nv_bfloat16 h2 = __float2bfloat16(y2);
    H[base + half]      = h1;
    H[base + half + 64] = h2;
    L[base + half]      = __float2bfloat16(y1 - __bfloat162float(h1));
    L[base + half + 64] = __float2bfloat16(y2 - __bfloat162float(h2));
}

// ---------------------------------------------------------------------------
// FlashAttention-2 mma.sync bf16 split (proven R3 kernel); epilogue now emits
// hi/lo bf16 for the Wo tensor-core GEMM.
// ---------------------------------------------------------------------------
#define ATT_SMEM 196608

__global__ void __launch_bounds__(256) attn_mma()
{
    extern __shared__ __align__(1024) char smdyn[];
    const int qb = blockIdx.x, h = blockIdx.y, b = blockIdx.z;
    const int kvh = h / GRP;
    const int tid = threadIdx.x, w = tid >> 5, l = tid & 31;
    const uint32_t sb = su32(smdyn);
    const uint32_t Qh_s = sb;
    const uint32_t KV0  = sb + 65536;

    {
        const __nv_bfloat16* qh = g_Qh + (size_t)(b * SS + qb * 128) * HID + h * HD;
        const __nv_bfloat16* ql = g_Ql + (size_t)(b * SS + qb * 128) * HID + h * HD;
        #pragma unroll
        for (int t = 0; t < 8; t++) {
            int j = tid + t * 256;
            int r = j >> 4, c = j & 15;
            uint32_t o = swz256((uint32_t)(r * 256 + c * 16));
            cp16(Qh_s + o,         (const void*)(qh + (size_t)r * HID + c * 8));
            cp16(Qh_s + 32768 + o, (const void*)(ql + (size_t)r * HID + c * 8));
        }
        CP_COMMIT();
    }

    const int NT = 2 * qb + 2;
    auto loadKV = [&](int kt) {
        const uint32_t st = KV0 + (uint32_t)(kt & 1) * 65536;
        const size_t rb = (size_t)(b * SS + kt * 64) * KVD + kvh * HD;
        #pragma unroll
        for (int t = 0; t < 4; t++) {
            int j = tid + t * 256;
            int r = j >> 4, c = j & 15;
            uint32_t o = swz256((uint32_t)(r * 256 + c * 16));
            size_t g = rb + (size_t)r * KVD + c * 8;
            cp16(st +         o, (const void*)(g_Kh + g));
            cp16(st + 16384 + o, (const void*)(g_Kl + g));
            cp16(st + 32768 + o, (const void*)(g_Vh + g));
            cp16(st + 49152 + o, (const void*)(g_Vl + g));
        }
        CP_COMMIT();
    };
    loadKV(0);

    const int m0 = w * 16;
    const int qg0 = qb * 128 + m0 + (l >> 2);
    float O[16][4];
    #pragma unroll
    for (int f = 0; f < 16; f++)
        { O[f][0] = 0.f; O[f][1] = 0.f; O[f][2] = 0.f; O[f][3] = 0.f; }
    float mr0 = -1e30f, mr1 = -1e30f, sl0 = 0.f, sl1 = 0.f;

    for (int kt = 0; kt < NT; kt++) {
        if (kt + 1 < NT) {
            loadKV(kt + 1);
            asm volatile("cp.async.wait_group 1;\n");
        } else {
            asm volatile("cp.async.wait_group 0;\n");
        }
        __syncthreads();

        const uint32_t st = KV0 + (uint32_t)(kt & 1) * 65536;

        float s[8][4];
        #pragma unroll
        for (int nb = 0; nb < 8; nb++)
            { s[nb][0] = 0.f; s[nb][1] = 0.f; s[nb][2] = 0.f; s[nb][3] = 0.f; }

        #pragma unroll
        for (int ks = 0; ks < 8; ks++) {
            uint32_t aQh[4], aQl[4];
            uint32_t aaddr = Qh_s + swz256(
                (uint32_t)((m0 + (l & 15)) * 256 + ks * 32 + ((l & 16) ? 16 : 0)));
            LDSM_X4(aQh, aaddr);
            LDSM_X4(aQl, aaddr + 32768);
            #pragma unroll
            for (int nb2 = 0; nb2 < 4; nb2++) {
                uint32_t brow = (uint32_t)(nb2 * 16 + (l & 7) + ((l & 16) ? 8 : 0));
                uint32_t baddr = st + swz256(brow * 256 + ks * 32 + ((l & 8) ? 16 : 0));
                uint32_t bh[4], bl[4];
                LDSM_X4(bh, baddr);
                LDSM_X4(bl, baddr + 16384);
                MMA4(s[2*nb2],   aQh, bh[0], bh[1]);
                MMA4(s[2*nb2+1], aQh, bh[2], bh[3]);
                MMA4(s[2*nb2],   aQh, bl[0], bl[1]);
                MMA4(s[2*nb2+1], aQh, bl[2], bl[3]);
                MMA4(s[2*nb2],   aQl, bh[0], bh[1]);
                MMA4(s[2*nb2+1], aQl, bh[2], bh[3]);
            }
        }

        const int kgb = kt * 64 + (l & 3) * 2;
        float mx0 = -1e30f, mx1 = -1e30f;
        #pragma unroll
        for (int nb = 0; nb < 8; nb++) {
            int kg = kgb + nb * 8;
            if (kg     > qg0)     s[nb][0] = -1e30f;
            if (kg + 1 > qg0)     s[nb][1] = -1e30f;
            if (kg     > qg0 + 8) s[nb][2] = -1e30f;
            if (kg + 1 > qg0 + 8) s[nb][3] = -1e30f;
            mx0 = fmaxf(mx0, fmaxf(s[nb][0], s[nb][1]));
            mx1 = fmaxf(mx1, fmaxf(s[nb][2], s[nb][3]));
        }
        mx0 = fmaxf(mx0, __shfl_xor_sync(0xffffffffu, mx0, 1));
        mx0 = fmaxf(mx0, __shfl_xor_sync(0xffffffffu, mx0, 2));
        mx1 = fmaxf(mx1, __shfl_xor_sync(0xffffffffu, mx1, 1));
        mx1 = fmaxf(mx1, __shfl_xor_sync(0xffffffffu, mx1, 2));

        float mn0 = fmaxf(mr0, mx0), mn1 = fmaxf(mr1, mx1);
        float al0 = __expf(mr0 - mn0), al1 = __expf(mr1 - mn1);
        mr0 = mn0; mr1 = mn1;
        float sum0 = 0.f, sum1 = 0.f;
        #pragma unroll
        for (int nb = 0; nb < 8; nb++) {
            s[nb][0] = __expf(s[nb][0] - mn0);
            s[nb][1] = __expf(s[nb][1] - mn0);
            s[nb][2] = __expf(s[nb][2] - mn1);
            s[nb][3] = __expf(s[nb][3] - mn1);
            sum0 += s[nb][0] + s[nb][1];
            sum1 += s[nb][2] + s[nb][3];
        }
        sum0 += __shfl_xor_sync(0xffffffffu, sum0, 1);
        sum0 += __shfl_xor_sync(0xffffffffu, sum0, 2);
        sum1 += __shfl_xor_sync(0xffffffffu, sum1, 1);
        sum1 += __shfl_xor_sync(0xffffffffu, sum1, 2);
        sl0 = sl0 * al0 + sum0;
        sl1 = sl1 * al1 + sum1;
        #pragma unroll
        for (int f = 0; f < 16; f++) {
            O[f][0] *= al0; O[f][1] *= al0; O[f][2] *= al1; O[f][3] *= al1;
        }

        #pragma unroll
        for (int j = 0; j < 4; j++) {
            uint32_t ph[4], pl[4];
            pk2(s[2*j][0],   s[2*j][1],   ph[0], pl[0]);
            pk2(s[2*j][2],   s[2*j][3],   ph[1], pl[1]);
            pk2(s[2*j+1][0], s[2*j+1][1], ph[2], pl[2]);
            pk2(s[2*j+1][2], s[2*j+1][3], ph[3], pl[3]);
            uint32_t vrow = (uint32_t)(j * 16 + (l & 7) + ((l & 8) ? 8 : 0));
            #pragma unroll
            for (int nb2 = 0; nb2 < 8; nb2++) {
                uint32_t vaddr = st + 32768 +
                    swz256(vrow * 256 + nb2 * 32 + ((l & 16) ? 16 : 0));
                uint32_t vh[4], vl[4];
                LDSM_X4T(vh, vaddr);
                LDSM_X4T(vl, vaddr + 16384);
                MMA4(O[2*nb2],   ph, vh[0], vh[1]);
                MMA4(O[2*nb2+1], ph, vh[2], vh[3]);
                MMA4(O[2*nb2],   ph, vl[0], vl[1]);
                MMA4(O[2*nb2+1], ph, vl[2], vl[3]);
                MMA4(O[2*nb2],   pl, vh[0], vh[1]);
                MMA4(O[2*nb2+1], pl, vh[2], vh[3]);
            }
        }
        __syncthreads();
    }

    // epilogue: normalize + split to hi/lo bf16
    const float i0 = 1.0f / sl0, i1 = 1.0f / sl1;
    size_t base0 = (size_t)(b * SS + qg0) * HID + (size_t)h * HD;
    size_t base1 = base0 + (size_t)8 * HID;
    #pragma unroll
    for (int nb = 0; nb < 16; nb++) {
        int col = nb * 8 + (l & 3) * 2;
        uint32_t hi, lo;
        pk2(O[nb][0] * i0, O[nb][1] * i0, hi, lo);
        *(uint32_t*)(g_Ath + base0 + col) = hi;
        *(uint32_t*)(g_Atl + base0 + col) = lo;
        pk2(O[nb][2] * i1, O[nb][3] * i1, hi, lo);
        *(uint32_t*)(g_Ath + base1 + col) = hi;
        *(uint32_t*)(g_Atl + base1 + col) = lo;
    }
}

// ---------------------------------------------------------------------------
extern "C" void kernel_launch(void* const* d_in, const int* in_sizes, int n_in,
                              void* d_out, int out_size)
{
    (void)in_sizes; (void)n_in; (void)out_size;
    const float* x  = (const float*)d_in[0];
    const float* Wq = (const float*)d_in[1];
    const float* Wk = (const float*)d_in[2];
    const float* Wv = (const float*)d_in[3];
    const float* Wo = (const float*)d_in[4];
    float* out = (float*)d_out;

    float *Qp, *Kp;
    __nv_bfloat16 *xh, *xl, *wqh, *wql, *wkh, *wkl, *wvh, *wvl, *woh, *wol;
    __nv_bfloat16 *qh, *ql, *kh, *kl, *vh, *vl, *ath, *atl;
    cudaGetSymbolAddress((void**)&Qp, g_Q);
    cudaGetSymbolAddress((void**)&Kp, g_K);
    cudaGetSymbolAddress((void**)&xh, g_xh);   cudaGetSymbolAddress((void**)&xl, g_xl);
    cudaGetSymbolAddress((void**)&wqh, g_Wqh); cudaGetSymbolAddress((void**)&wql, g_Wql);
    cudaGetSymbolAddress((void**)&wkh, g_Wkh); cudaGetSymbolAddress((void**)&wkl, g_Wkl);
    cudaGetSymbolAddress((void**)&wvh, g_Wvh); cudaGetSymbolAddress((void**)&wvl, g_Wvl);
    cudaGetSymbolAddress((void**)&woh, g_Woh); cudaGetSymbolAddress((void**)&wol, g_Wol);
    cudaGetSymbolAddress((void**)&qh, g_Qh);   cudaGetSymbolAddress((void**)&ql, g_Ql);
    cudaGetSymbolAddress((void**)&kh, g_Kh);   cudaGetSymbolAddress((void**)&kl, g_Kl);
    cudaGetSymbolAddress((void**)&vh, g_Vh);   cudaGetSymbolAddress((void**)&vl, g_Vl);
    cudaGetSymbolAddress((void**)&ath, g_Ath); cudaGetSymbolAddress((void**)&atl, g_Atl);

    cudaFuncSetAttribute(gemm_bf16s, cudaFuncAttributeMaxDynamicSharedMemorySize, GEMM_SMEM);
    cudaFuncSetAttribute(attn_mma, cudaFuncAttributeMaxDynamicSharedMemorySize, ATT_SMEM);

    rope_table_k<<<(SS * 64 + 255) / 256, 256>>>();

    cvt_hl<<<(MR * HID + 255) / 256, 256>>>(x,  xh,  xl,  MR * HID);
    cvt_hl<<<(HID * HID + 255) / 256, 256>>>(Wq, wqh, wql, HID * HID);
    cvt_hl<<<(HID * KVD + 255) / 256, 256>>>(Wk, wkh, wkl, HID * KVD);
    cvt_hl<<<(HID * KVD + 255) / 256, 256>>>(Wv, wvh, wvl, HID * KVD);
    cvt_hl<<<(HID * HID + 255) / 256, 256>>>(Wo, woh, wol, HID * HID);

    gemm_bf16s<<<dim3(HID / 128, MR / 128), 256, GEMM_SMEM>>>(
        xh, xl, wqh, wql, Qp, nullptr, nullptr, HID);
    gemm_bf16s<<<dim3(KVD / 128, MR / 128), 256, GEMM_SMEM>>>(
        xh, xl, wkh, wkl, Kp, nullptr, nullptr, KVD);
    gemm_bf16s<<<dim3(KVD / 128, MR / 128), 256, GEMM_SMEM>>>(
        xh, xl, wvh, wvl, nullptr, vh, vl, KVD);

    const float scale = 0.08838834764831845f;   // 1/sqrt(128)
    rope_split_k<<<(MR * NHQ  * 64 + 255) / 256, 256>>>(Qp, qh, ql, NHQ, scale);
    rope_split_k<<<(MR * NHKV * 64 + 255) / 256, 256>>>(Kp, kh, kl, NHKV, 1.0f);

    attn_mma<<<dim3(SS / 128, NHQ, BB), 256, ATT_SMEM>>>();

    gemm_bf16s<<<dim3(HID / 128, MR / 128), 256, GEMM_SMEM>>>(
        ath, atl, woh, wol, out, nullptr, nullptr, HID);
}